// round 12
// baseline (speedup 1.0000x reference)
#include <cuda_runtime.h>
#include <mma.h>

using namespace nvcuda;

#define NN 10000
#define NE 320000
#define DH 256
#define NC 40

// Static scratch (allowed).
__device__ __align__(16) float4 g_bufA[NN * DH / 4];
__device__ __align__(16) float4 g_bufB[NN * DH / 4];
__device__ int g_idx[2 * NE];      // [0,NE)=src, [NE,2NE)=dst (clean int32)
__device__ int g_deg[NN];
__device__ int g_off[NN + 1];
__device__ int g_cur[NN];
__device__ int g_esrc[NE];         // src ids grouped by dst (CSR payload)
__device__ int g_is64;

// ---------------------------------------------------------------------------
// Detect edge-index dtype (int64 vs int32) AND zero the degree histogram.
// ---------------------------------------------------------------------------
__global__ void detect_and_zero(const int* __restrict__ p)
{
    const int i = blockIdx.x * blockDim.x + threadIdx.x;
    if (i < NN) g_deg[i] = 0;
    if (i == 0) {
        int any_nonzero = 0;
        for (int k = 0; k < 64; k++)
            any_nonzero |= p[2 * k + 1];
        g_is64 = (any_nonzero == 0) ? 1 : 0;
    }
}

__global__ void convert_hist(const void* __restrict__ p)
{
    const int i = blockIdx.x * blockDim.x + threadIdx.x;
    if (i >= 2 * NE) return;
    int v;
    if (g_is64) v = (int)((const long long*)p)[i];
    else        v = ((const int*)p)[i];
    v = min(max(v, 0), NN - 1);
    g_idx[i] = v;
    if (i >= NE) atomicAdd(&g_deg[v], 1);
}

// ---------------------------------------------------------------------------
// Single-block exclusive scan: 1024 threads x 10 elements each.
// ---------------------------------------------------------------------------
__global__ void scan_deg_fast()
{
    const int t = threadIdx.x;
    const int lane = t & 31, warp = t >> 5;
    const int base = t * 10;

    int lexcl[10];
    int sum = 0;
#pragma unroll
    for (int i = 0; i < 10; i++) {
        const int idx = base + i;
        const int v = (idx < NN) ? __ldg(&g_deg[idx]) : 0;
        lexcl[i] = sum;
        sum += v;
    }

    int x = sum;
#pragma unroll
    for (int d = 1; d < 32; d <<= 1) {
        int y = __shfl_up_sync(0xffffffffu, x, d);
        if (lane >= d) x += y;
    }
    __shared__ int wsum[32];
    if (lane == 31) wsum[warp] = x;
    __syncthreads();
    if (warp == 0) {
        int w = wsum[lane];
#pragma unroll
        for (int d = 1; d < 32; d <<= 1) {
            int y = __shfl_up_sync(0xffffffffu, w, d);
            if (lane >= d) w += y;
        }
        wsum[lane] = w;
    }
    __syncthreads();

    const int texcl = (x - sum) + (warp ? wsum[warp - 1] : 0);
#pragma unroll
    for (int i = 0; i < 10; i++) {
        const int idx = base + i;
        if (idx < NN) {
            const int o = texcl + lexcl[i];
            g_off[idx] = o;
            g_cur[idx] = o;
        }
    }
    if (t == 1023) g_off[NN] = wsum[31];
}

__global__ void fill_csr()
{
    const int e = blockIdx.x * blockDim.x + threadIdx.x;
    if (e >= NE) return;
    const int dst = g_idx[NE + e];
    const int pos = atomicAdd(&g_cur[dst], 1);
    g_esrc[pos] = g_idx[e];
}

// ---------------------------------------------------------------------------
// 3xTF32 tensor-core GEMM (N=K=256): C = act(A) @ B + bias.
// 128x64 block tile, 8 warps (4 along M x 2 along N), each warp 32x32,
// 2x2 wmma m16n16k8 tiles, BK=32, register-prefetch pipeline.
// Split precision: a=ah+al, b=bh+bl; C += ah*bh + ah*bl + al*bh (fp32-grade).
// ---------------------------------------------------------------------------
#define AS_STRIDE 40   // 128 x BK tile, row-major [m][k], 160B rows (16B mult)
#define BS_STRIDE 72   // BK x 64 tile, row-major [k][n], 288B rows (16B mult)

template<bool RELU_IN>
__global__ void __launch_bounds__(256)
gemm_tf32(const float* __restrict__ A, const float* __restrict__ B,
          const float* __restrict__ bias, float* __restrict__ C, int M)
{
    constexpr int KD = 256, ND = 256, BK = 32;
    __shared__ __align__(16) float smem[128 * BS_STRIDE];  // 36864B, reused
    float* As = smem;                       // 128*40 = 5120 floats
    float* Bs = smem + 128 * AS_STRIDE;     // 32*72  = 2304 floats

    const int tid = threadIdx.x;
    const int wid = tid >> 5;
    const int wm = wid & 3;          // warp row   (4 x 32 = 128)
    const int wn = wid >> 2;         // warp col   (2 x 32 = 64)
    const int m0 = blockIdx.y * 128;
    const int n0 = blockIdx.x * 64;

    using FragA = wmma::fragment<wmma::matrix_a, 16, 16, 8, wmma::precision::tf32, wmma::row_major>;
    using FragB = wmma::fragment<wmma::matrix_b, 16, 16, 8, wmma::precision::tf32, wmma::row_major>;
    using FragC = wmma::fragment<wmma::accumulator, 16, 16, 8, float>;

    FragC acc[2][2];
#pragma unroll
    for (int i = 0; i < 2; i++)
#pragma unroll
        for (int j = 0; j < 2; j++) wmma::fill_fragment(acc[i][j], 0.f);

    const float4 z4 = make_float4(0.f, 0.f, 0.f, 0.f);
    // A: 128x32 = 1024 float4 -> 4/thread. B: 32x64 = 512 float4 -> 2/thread.
    float4 ra[4], rb[2];

#pragma unroll
    for (int i = 0; i < 4; i++) {
        const int f4 = tid + i * 256;
        const int row = f4 >> 3, c4 = f4 & 7;
        ra[i] = (m0 + row < M)
            ? *reinterpret_cast<const float4*>(&A[(size_t)(m0 + row) * KD + c4 * 4]) : z4;
    }
#pragma unroll
    for (int i = 0; i < 2; i++) {
        const int f4 = tid + i * 256;
        const int row = f4 >> 4, c4 = f4 & 15;
        rb[i] = *reinterpret_cast<const float4*>(&B[(size_t)row * ND + n0 + c4 * 4]);
    }

    for (int s = 0; s < KD / BK; s++) {
#pragma unroll
        for (int i = 0; i < 4; i++) {
            const int f4 = tid + i * 256;
            const int row = f4 >> 3, c4 = f4 & 7;
            float4 v = ra[i];
            if (RELU_IN) {
                v.x = fmaxf(v.x, 0.f); v.y = fmaxf(v.y, 0.f);
                v.z = fmaxf(v.z, 0.f); v.w = fmaxf(v.w, 0.f);
            }
            *reinterpret_cast<float4*>(&As[row * AS_STRIDE + c4 * 4]) = v;
        }
#pragma unroll
        for (int i = 0; i < 2; i++) {
            const int f4 = tid + i * 256;
            const int row = f4 >> 4, c4 = f4 & 15;
            *reinterpret_cast<float4*>(&Bs[row * BS_STRIDE + c4 * 4]) = rb[i];
        }
        __syncthreads();

        if (s + 1 < KD / BK) {
            const int kn = (s + 1) * BK;
#pragma unroll
            for (int i = 0; i < 4; i++) {
                const int f4 = tid + i * 256;
                const int row = f4 >> 3, c4 = f4 & 7;
                ra[i] = (m0 + row < M)
                    ? *reinterpret_cast<const float4*>(&A[(size_t)(m0 + row) * KD + kn + c4 * 4]) : z4;
            }
#pragma unroll
            for (int i = 0; i < 2; i++) {
                const int f4 = tid + i * 256;
                const int row = f4 >> 4, c4 = f4 & 15;
                rb[i] = *reinterpret_cast<const float4*>(&B[(size_t)(kn + row) * ND + n0 + c4 * 4]);
            }
        }

#pragma unroll
        for (int k8 = 0; k8 < BK; k8 += 8) {
            FragA ah[2], al[2];
            FragB bh[2], bl[2];
#pragma unroll
            for (int mi = 0; mi < 2; mi++) {
                wmma::load_matrix_sync(ah[mi], &As[(wm * 32 + mi * 16) * AS_STRIDE + k8], AS_STRIDE);
#pragma unroll
                for (int e = 0; e < ah[mi].num_elements; e++) {
                    const float v = ah[mi].x[e];
                    const float vh = wmma::__float_to_tf32(v);
                    ah[mi].x[e] = vh;
                    al[mi].x[e] = wmma::__float_to_tf32(v - vh);
                }
            }
#pragma unroll
            for (int ni = 0; ni < 2; ni++) {
                wmma::load_matrix_sync(bh[ni], &Bs[k8 * BS_STRIDE + wn * 32 + ni * 16], BS_STRIDE);
#pragma unroll
                for (int e = 0; e < bh[ni].num_elements; e++) {
                    const float v = bh[ni].x[e];
                    const float vh = wmma::__float_to_tf32(v);
                    bh[ni].x[e] = vh;
                    bl[ni].x[e] = wmma::__float_to_tf32(v - vh);
                }
            }
#pragma unroll
            for (int mi = 0; mi < 2; mi++)
#pragma unroll
                for (int ni = 0; ni < 2; ni++) {
                    wmma::mma_sync(acc[mi][ni], ah[mi], bl[ni], acc[mi][ni]);
                    wmma::mma_sync(acc[mi][ni], al[mi], bh[ni], acc[mi][ni]);
                    wmma::mma_sync(acc[mi][ni], ah[mi], bh[ni], acc[mi][ni]);
                }
        }
        __syncthreads();
    }

    // Epilogue: stage 128x64 result in smem (stride 72), add bias, store.
    float* Cs = smem;
#pragma unroll
    for (int mi = 0; mi < 2; mi++)
#pragma unroll
        for (int ni = 0; ni < 2; ni++)
            wmma::store_matrix_sync(&Cs[(wm * 32 + mi * 16) * BS_STRIDE + wn * 32 + ni * 16],
                                    acc[mi][ni], BS_STRIDE, wmma::mem_row_major);
    __syncthreads();

#pragma unroll
    for (int i = 0; i < 8; i++) {
        const int f4 = tid + i * 256;            // 2048 float4 total
        const int row = f4 >> 4, c4 = f4 & 15;
        if (m0 + row >= M) continue;
        const float4 v = *reinterpret_cast<const float4*>(&Cs[row * BS_STRIDE + c4 * 4]);
        const float4 bi = *reinterpret_cast<const float4*>(&bias[n0 + c4 * 4]);
        float4 o = make_float4(v.x + bi.x, v.y + bi.y, v.z + bi.z, v.w + bi.w);
        *reinterpret_cast<float4*>(&C[(size_t)(m0 + row) * ND + n0 + c4 * 4]) = o;
    }
}

// ---------------------------------------------------------------------------
// Tiled SGEMM 64x64 (layer 3, N=40): C = act(A) @ B + bias.
// ---------------------------------------------------------------------------
template<bool RELU_IN>
__global__ void gemm64(const float* __restrict__ A, const float* __restrict__ B,
                       const float* __restrict__ bias, float* __restrict__ C,
                       int M, int N, int K)
{
    __shared__ float As[16][64];
    __shared__ float Bs[16][64];
    const int tid = threadIdx.x;
    const int ty = tid >> 4, tx = tid & 15;
    const int m0 = blockIdx.y * 64;
    const int n0 = blockIdx.x * 64;

    float acc[4][4];
#pragma unroll
    for (int i = 0; i < 4; i++)
#pragma unroll
        for (int j = 0; j < 4; j++) acc[i][j] = 0.f;

    const int la = tid * 4;
    const int ar = la >> 4, ac = la & 15;
    const int br = la >> 6, bc = la & 63;
    const int grow = m0 + ar;
    const int gcol = n0 + bc;

    float4 va = make_float4(0.f, 0.f, 0.f, 0.f);
    if (grow < M)
        va = *reinterpret_cast<const float4*>(&A[(size_t)grow * K + ac]);
    float4 vb = make_float4(0.f, 0.f, 0.f, 0.f);
    if (gcol < N)
        vb = *reinterpret_cast<const float4*>(&B[(size_t)br * N + gcol]);

    for (int k0 = 0; k0 < K; k0 += 16) {
        float4 sa = va;
        if (RELU_IN) {
            sa.x = fmaxf(sa.x, 0.f); sa.y = fmaxf(sa.y, 0.f);
            sa.z = fmaxf(sa.z, 0.f); sa.w = fmaxf(sa.w, 0.f);
        }
        As[ac + 0][ar] = sa.x; As[ac + 1][ar] = sa.y;
        As[ac + 2][ar] = sa.z; As[ac + 3][ar] = sa.w;
        Bs[br][bc + 0] = vb.x; Bs[br][bc + 1] = vb.y;
        Bs[br][bc + 2] = vb.z; Bs[br][bc + 3] = vb.w;
        __syncthreads();

        if (k0 + 16 < K) {
            va = make_float4(0.f, 0.f, 0.f, 0.f);
            if (grow < M)
                va = *reinterpret_cast<const float4*>(&A[(size_t)grow * K + k0 + 16 + ac]);
            vb = make_float4(0.f, 0.f, 0.f, 0.f);
            if (gcol < N)
                vb = *reinterpret_cast<const float4*>(&B[(size_t)(k0 + 16 + br) * N + gcol]);
        }

#pragma unroll
        for (int k = 0; k < 16; k++) {
            const float4 a4 = *reinterpret_cast<const float4*>(&As[k][ty * 4]);
            const float4 b4 = *reinterpret_cast<const float4*>(&Bs[k][tx * 4]);
            const float a[4] = {a4.x, a4.y, a4.z, a4.w};
            const float b[4] = {b4.x, b4.y, b4.z, b4.w};
#pragma unroll
            for (int i = 0; i < 4; i++)
#pragma unroll
                for (int j = 0; j < 4; j++)
                    acc[i][j] += a[i] * b[j];
        }
        __syncthreads();
    }

#pragma unroll
    for (int i = 0; i < 4; i++) {
        int row = m0 + ty * 4 + i;
        if (row >= M) continue;
#pragma unroll
        for (int j = 0; j < 4; j++) {
            int col = n0 + tx * 4 + j;
            if (col < N)
                C[(size_t)row * N + col] = acc[i][j] + bias[col];
        }
    }
}

// ---------------------------------------------------------------------------
// Pull-mode aggregation, D=256, vectorized. No atomics.
// ---------------------------------------------------------------------------
__global__ void agg256v(const float4* __restrict__ h4, float4* __restrict__ out4)
{
    const int tid = threadIdx.x;
    const int node = blockIdx.x * 4 + (tid >> 6);
    const int f4 = tid & 63;
    if (node >= NN) return;
    const int beg = g_off[node], end = g_off[node + 1];

    float4 acc = make_float4(0.f, 0.f, 0.f, 0.f);
    int e = beg;
    for (; e + 4 <= end; e += 4) {
        const int s0 = g_esrc[e + 0], s1 = g_esrc[e + 1];
        const int s2 = g_esrc[e + 2], s3 = g_esrc[e + 3];
        const float4 v0 = h4[(size_t)s0 * 64 + f4];
        const float4 v1 = h4[(size_t)s1 * 64 + f4];
        const float4 v2 = h4[(size_t)s2 * 64 + f4];
        const float4 v3 = h4[(size_t)s3 * 64 + f4];
        acc.x += (v0.x + v1.x) + (v2.x + v3.x);
        acc.y += (v0.y + v1.y) + (v2.y + v3.y);
        acc.z += (v0.z + v1.z) + (v2.z + v3.z);
        acc.w += (v0.w + v1.w) + (v2.w + v3.w);
    }
    for (; e < end; e++) {
        const float4 v = h4[(size_t)g_esrc[e] * 64 + f4];
        acc.x += v.x; acc.y += v.y; acc.z += v.z; acc.w += v.w;
    }
    out4[(size_t)node * 64 + f4] = acc;
}

// ---------------------------------------------------------------------------
// Pull-mode aggregation, D=40 (+ReLU): 8 nodes per 320-thread block.
// ---------------------------------------------------------------------------
__global__ void agg40_relu(const float* __restrict__ h, float* __restrict__ out)
{
    const int tid = threadIdx.x;
    const int node = blockIdx.x * 8 + tid / NC;
    const int f = tid % NC;
    if (node >= NN) return;
    const int beg = g_off[node], end = g_off[node + 1];

    float acc = 0.f;
    int e = beg;
    for (; e + 4 <= end; e += 4) {
        const int s0 = g_esrc[e + 0], s1 = g_esrc[e + 1];
        const int s2 = g_esrc[e + 2], s3 = g_esrc[e + 3];
        const float v0 = h[(size_t)s0 * NC + f];
        const float v1 = h[(size_t)s1 * NC + f];
        const float v2 = h[(size_t)s2 * NC + f];
        const float v3 = h[(size_t)s3 * NC + f];
        acc += (v0 + v1) + (v2 + v3);
    }
    for (; e < end; e++)
        acc += h[(size_t)g_esrc[e] * NC + f];
    out[(size_t)node * NC + f] = fmaxf(acc, 0.f);
}

// ---------------------------------------------------------------------------
extern "C" void kernel_launch(void* const* d_in, const int* in_sizes, int n_in,
                              void* d_out, int out_size)
{
    const float* x  = (const float*)d_in[0];
    const void*  ei = d_in[1];
    const float* W1 = (const float*)d_in[2];
    const float* b1 = (const float*)d_in[3];
    const float* W2 = (const float*)d_in[4];
    const float* b2 = (const float*)d_in[5];
    const float* W3 = (const float*)d_in[6];
    const float* b3 = (const float*)d_in[7];
    float* out = (float*)d_out;

    float4 *bufA, *bufB;
    cudaGetSymbolAddress((void**)&bufA, g_bufA);
    cudaGetSymbolAddress((void**)&bufB, g_bufB);

    static cudaStream_t s_side = nullptr;
    static cudaEvent_t ev_fork = nullptr, ev_join = nullptr;
    if (s_side == nullptr) {
        cudaStreamCreateWithFlags(&s_side, cudaStreamNonBlocking);
        cudaEventCreateWithFlags(&ev_fork, cudaEventDisableTiming);
        cudaEventCreateWithFlags(&ev_join, cudaEventDisableTiming);
    }

    const dim3 blk(256);
    const dim3 gHid(DH / 64, (NN + 127) / 128);       // (4, 79) = 316 blocks
    const dim3 gCls((NC + 63) / 64, (NN + 63) / 64);  // (1, 157)

    // Fork: CSR build on side stream, layer-1 GEMM on main stream.
    cudaEventRecord(ev_fork, 0);
    cudaStreamWaitEvent(s_side, ev_fork, 0);

    detect_and_zero<<<(NN + 255) / 256, blk, 0, s_side>>>((const int*)ei);
    convert_hist<<<(2 * NE + 255) / 256, blk, 0, s_side>>>(ei);
    scan_deg_fast<<<1, 1024, 0, s_side>>>();
    fill_csr<<<(NE + 255) / 256, blk, 0, s_side>>>();
    cudaEventRecord(ev_join, s_side);

    // Layer 1 GEMM (tensor cores) overlaps the CSR build.
    gemm_tf32<false><<<gHid, blk>>>(x, W1, b1, (float*)bufB, NN);

    // Join: aggregation needs both GEMM1 output and the CSR.
    cudaStreamWaitEvent(0, ev_join, 0);
    agg256v<<<(NN + 3) / 4, blk>>>(bufB, bufA);

    // Layer 2
    gemm_tf32<true><<<gHid, blk>>>((const float*)bufA, W2, b2, (float*)bufB, NN);
    agg256v<<<(NN + 3) / 4, blk>>>(bufB, bufA);

    // Layer 3
    gemm64<true><<<gCls, blk>>>((const float*)bufA, W3, b3, (float*)bufB, NN, NC, DH);
    agg40_relu<<<(NN + 7) / 8, 320>>>((const float*)bufB, out);
}

// round 13
// speedup vs baseline: 1.1780x; 1.1780x over previous
#include <cuda_runtime.h>

#define NN 10000
#define NE 320000
#define DH 256
#define NC 40
#define NH 5000   // node/row split for pipelining

// Static scratch (allowed): 3 rotating feature buffers + CSR.
__device__ __align__(16) float4 g_buf0[NN * DH / 4];
__device__ __align__(16) float4 g_buf1[NN * DH / 4];
__device__ __align__(16) float4 g_buf2[NN * DH / 4];
__device__ int g_idx[2 * NE];      // [0,NE)=src, [NE,2NE)=dst (clean int32)
__device__ int g_deg[NN];
__device__ int g_off[NN + 1];
__device__ int g_cur[NN];
__device__ int g_esrc[NE];         // src ids grouped by dst (CSR payload)
__device__ int g_is64;

// ---------------------------------------------------------------------------
// Detect edge-index dtype (int64 vs int32) AND zero the degree histogram.
// ---------------------------------------------------------------------------
__global__ void detect_and_zero(const int* __restrict__ p)
{
    const int i = blockIdx.x * blockDim.x + threadIdx.x;
    if (i < NN) g_deg[i] = 0;
    if (i == 0) {
        int any_nonzero = 0;
        for (int k = 0; k < 64; k++)
            any_nonzero |= p[2 * k + 1];
        g_is64 = (any_nonzero == 0) ? 1 : 0;
    }
}

__global__ void convert_hist(const void* __restrict__ p)
{
    const int i = blockIdx.x * blockDim.x + threadIdx.x;
    if (i >= 2 * NE) return;
    int v;
    if (g_is64) v = (int)((const long long*)p)[i];
    else        v = ((const int*)p)[i];
    v = min(max(v, 0), NN - 1);
    g_idx[i] = v;
    if (i >= NE) atomicAdd(&g_deg[v], 1);
}

// ---------------------------------------------------------------------------
// Single-block exclusive scan: 1024 threads x 10 elements each.
// ---------------------------------------------------------------------------
__global__ void scan_deg_fast()
{
    const int t = threadIdx.x;
    const int lane = t & 31, warp = t >> 5;
    const int base = t * 10;

    int lexcl[10];
    int sum = 0;
#pragma unroll
    for (int i = 0; i < 10; i++) {
        const int idx = base + i;
        const int v = (idx < NN) ? __ldg(&g_deg[idx]) : 0;
        lexcl[i] = sum;
        sum += v;
    }

    int x = sum;
#pragma unroll
    for (int d = 1; d < 32; d <<= 1) {
        int y = __shfl_up_sync(0xffffffffu, x, d);
        if (lane >= d) x += y;
    }
    __shared__ int wsum[32];
    if (lane == 31) wsum[warp] = x;
    __syncthreads();
    if (warp == 0) {
        int w = wsum[lane];
#pragma unroll
        for (int d = 1; d < 32; d <<= 1) {
            int y = __shfl_up_sync(0xffffffffu, w, d);
            if (lane >= d) w += y;
        }
        wsum[lane] = w;
    }
    __syncthreads();

    const int texcl = (x - sum) + (warp ? wsum[warp - 1] : 0);
#pragma unroll
    for (int i = 0; i < 10; i++) {
        const int idx = base + i;
        if (idx < NN) {
            const int o = texcl + lexcl[i];
            g_off[idx] = o;
            g_cur[idx] = o;
        }
    }
    if (t == 1023) g_off[NN] = wsum[31];
}

__global__ void fill_csr()
{
    const int e = blockIdx.x * blockDim.x + threadIdx.x;
    if (e >= NE) return;
    const int dst = g_idx[NE + e];
    const int pos = atomicAdd(&g_cur[dst], 1);
    g_esrc[pos] = g_idx[e];
}

// ---------------------------------------------------------------------------
// 128x64 tiled SGEMM for N=K=256: C = act(A) @ B + bias.
// 256 threads, 8x4 microtile, BK=16, register-prefetch pipeline.
// A/C are row-offset pointers; M = row count for this launch.
// ---------------------------------------------------------------------------
template<bool RELU_IN>
__global__ void gemm128x64(const float* __restrict__ A, const float* __restrict__ B,
                           const float* __restrict__ bias, float* __restrict__ C,
                           int M)
{
    constexpr int KD = 256;
    constexpr int ND = 256;
    __shared__ float As[16][132];   // [k][m] transposed, padded stride
    __shared__ float Bs[16][64];    // [k][n]

    const int tid = threadIdx.x;
    const int ty = tid >> 4, tx = tid & 15;
    const int m0 = blockIdx.y * 128;
    const int n0 = blockIdx.x * 64;

    const int a_row0 = (tid + 0)   >> 2, a_c40 = (tid + 0)   & 3;
    const int a_row1 = (tid + 256) >> 2, a_c41 = (tid + 256) & 3;
    const int b_row  = tid >> 4,         b_c4  = tid & 15;

    float acc[8][4];
#pragma unroll
    for (int i = 0; i < 8; i++)
#pragma unroll
        for (int j = 0; j < 4; j++) acc[i][j] = 0.f;

    const float4 z4 = make_float4(0.f, 0.f, 0.f, 0.f);
    float4 ra0 = z4, ra1 = z4, rb;

    if (m0 + a_row0 < M)
        ra0 = *reinterpret_cast<const float4*>(&A[(size_t)(m0 + a_row0) * KD + a_c40 * 4]);
    if (m0 + a_row1 < M)
        ra1 = *reinterpret_cast<const float4*>(&A[(size_t)(m0 + a_row1) * KD + a_c41 * 4]);
    rb = *reinterpret_cast<const float4*>(&B[(size_t)b_row * ND + n0 + b_c4 * 4]);

    for (int k0 = 0; k0 < KD; k0 += 16) {
        float4 sa0 = ra0, sa1 = ra1;
        if (RELU_IN) {
            sa0.x = fmaxf(sa0.x, 0.f); sa0.y = fmaxf(sa0.y, 0.f);
            sa0.z = fmaxf(sa0.z, 0.f); sa0.w = fmaxf(sa0.w, 0.f);
            sa1.x = fmaxf(sa1.x, 0.f); sa1.y = fmaxf(sa1.y, 0.f);
            sa1.z = fmaxf(sa1.z, 0.f); sa1.w = fmaxf(sa1.w, 0.f);
        }
        As[a_c40 * 4 + 0][a_row0] = sa0.x; As[a_c40 * 4 + 1][a_row0] = sa0.y;
        As[a_c40 * 4 + 2][a_row0] = sa0.z; As[a_c40 * 4 + 3][a_row0] = sa0.w;
        As[a_c41 * 4 + 0][a_row1] = sa1.x; As[a_c41 * 4 + 1][a_row1] = sa1.y;
        As[a_c41 * 4 + 2][a_row1] = sa1.z; As[a_c41 * 4 + 3][a_row1] = sa1.w;
        *reinterpret_cast<float4*>(&Bs[b_row][b_c4 * 4]) = rb;
        __syncthreads();

        if (k0 + 16 < KD) {
            const int kn = k0 + 16;
            ra0 = z4; ra1 = z4;
            if (m0 + a_row0 < M)
                ra0 = *reinterpret_cast<const float4*>(&A[(size_t)(m0 + a_row0) * KD + kn + a_c40 * 4]);
            if (m0 + a_row1 < M)
                ra1 = *reinterpret_cast<const float4*>(&A[(size_t)(m0 + a_row1) * KD + kn + a_c41 * 4]);
            rb = *reinterpret_cast<const float4*>(&B[(size_t)(kn + b_row) * ND + n0 + b_c4 * 4]);
        }

#pragma unroll
        for (int k = 0; k < 16; k++) {
            const float4 a0 = *reinterpret_cast<const float4*>(&As[k][ty * 8]);
            const float4 a1 = *reinterpret_cast<const float4*>(&As[k][ty * 8 + 4]);
            const float4 b4 = *reinterpret_cast<const float4*>(&Bs[k][tx * 4]);
            const float a[8] = {a0.x, a0.y, a0.z, a0.w, a1.x, a1.y, a1.z, a1.w};
            const float b[4] = {b4.x, b4.y, b4.z, b4.w};
#pragma unroll
            for (int i = 0; i < 8; i++)
#pragma unroll
                for (int j = 0; j < 4; j++)
                    acc[i][j] += a[i] * b[j];
        }
        __syncthreads();
    }

    const float4 bi = *reinterpret_cast<const float4*>(&bias[n0 + tx * 4]);
#pragma unroll
    for (int i = 0; i < 8; i++) {
        const int row = m0 + ty * 8 + i;
        if (row >= M) continue;
        float4 o = make_float4(acc[i][0] + bi.x, acc[i][1] + bi.y,
                               acc[i][2] + bi.z, acc[i][3] + bi.w);
        *reinterpret_cast<float4*>(&C[(size_t)row * ND + n0 + tx * 4]) = o;
    }
}

// ---------------------------------------------------------------------------
// Tiled SGEMM 64x64 (layer 3, N=40): C = act(A) @ B + bias.
// A/C row-offset pointers; M = row count.
// ---------------------------------------------------------------------------
template<bool RELU_IN>
__global__ void gemm64(const float* __restrict__ A, const float* __restrict__ B,
                       const float* __restrict__ bias, float* __restrict__ C,
                       int M, int N, int K)
{
    __shared__ float As[16][64];
    __shared__ float Bs[16][64];
    const int tid = threadIdx.x;
    const int ty = tid >> 4, tx = tid & 15;
    const int m0 = blockIdx.y * 64;
    const int n0 = blockIdx.x * 64;

    float acc[4][4];
#pragma unroll
    for (int i = 0; i < 4; i++)
#pragma unroll
        for (int j = 0; j < 4; j++) acc[i][j] = 0.f;

    const int la = tid * 4;
    const int ar = la >> 4, ac = la & 15;
    const int br = la >> 6, bc = la & 63;
    const int grow = m0 + ar;
    const int gcol = n0 + bc;

    float4 va = make_float4(0.f, 0.f, 0.f, 0.f);
    if (grow < M)
        va = *reinterpret_cast<const float4*>(&A[(size_t)grow * K + ac]);
    float4 vb = make_float4(0.f, 0.f, 0.f, 0.f);
    if (gcol < N)
        vb = *reinterpret_cast<const float4*>(&B[(size_t)br * N + gcol]);

    for (int k0 = 0; k0 < K; k0 += 16) {
        float4 sa = va;
        if (RELU_IN) {
            sa.x = fmaxf(sa.x, 0.f); sa.y = fmaxf(sa.y, 0.f);
            sa.z = fmaxf(sa.z, 0.f); sa.w = fmaxf(sa.w, 0.f);
        }
        As[ac + 0][ar] = sa.x; As[ac + 1][ar] = sa.y;
        As[ac + 2][ar] = sa.z; As[ac + 3][ar] = sa.w;
        Bs[br][bc + 0] = vb.x; Bs[br][bc + 1] = vb.y;
        Bs[br][bc + 2] = vb.z; Bs[br][bc + 3] = vb.w;
        __syncthreads();

        if (k0 + 16 < K) {
            va = make_float4(0.f, 0.f, 0.f, 0.f);
            if (grow < M)
                va = *reinterpret_cast<const float4*>(&A[(size_t)grow * K + k0 + 16 + ac]);
            vb = make_float4(0.f, 0.f, 0.f, 0.f);
            if (gcol < N)
                vb = *reinterpret_cast<const float4*>(&B[(size_t)(k0 + 16 + br) * N + gcol]);
        }

#pragma unroll
        for (int k = 0; k < 16; k++) {
            const float4 a4 = *reinterpret_cast<const float4*>(&As[k][ty * 4]);
            const float4 b4 = *reinterpret_cast<const float4*>(&Bs[k][tx * 4]);
            const float a[4] = {a4.x, a4.y, a4.z, a4.w};
            const float b[4] = {b4.x, b4.y, b4.z, b4.w};
#pragma unroll
            for (int i = 0; i < 4; i++)
#pragma unroll
                for (int j = 0; j < 4; j++)
                    acc[i][j] += a[i] * b[j];
        }
        __syncthreads();
    }

#pragma unroll
    for (int i = 0; i < 4; i++) {
        int row = m0 + ty * 4 + i;
        if (row >= M) continue;
#pragma unroll
        for (int j = 0; j < 4; j++) {
            int col = n0 + tx * 4 + j;
            if (col < N)
                C[(size_t)row * N + col] = acc[i][j] + bias[col];
        }
    }
}

// ---------------------------------------------------------------------------
// Pull-mode aggregation, D=256, vectorized, node range [beg, beg+cnt).
// ---------------------------------------------------------------------------
__global__ void agg256v(const float4* __restrict__ h4, float4* __restrict__ out4,
                        int nbeg, int ncnt)
{
    const int tid = threadIdx.x;
    const int node = nbeg + blockIdx.x * 4 + (tid >> 6);
    const int f4 = tid & 63;
    if (node >= nbeg + ncnt) return;
    const int beg = g_off[node], end = g_off[node + 1];

    float4 acc = make_float4(0.f, 0.f, 0.f, 0.f);
    int e = beg;
    for (; e + 4 <= end; e += 4) {
        const int s0 = g_esrc[e + 0], s1 = g_esrc[e + 1];
        const int s2 = g_esrc[e + 2], s3 = g_esrc[e + 3];
        const float4 v0 = h4[(size_t)s0 * 64 + f4];
        const float4 v1 = h4[(size_t)s1 * 64 + f4];
        const float4 v2 = h4[(size_t)s2 * 64 + f4];
        const float4 v3 = h4[(size_t)s3 * 64 + f4];
        acc.x += (v0.x + v1.x) + (v2.x + v3.x);
        acc.y += (v0.y + v1.y) + (v2.y + v3.y);
        acc.z += (v0.z + v1.z) + (v2.z + v3.z);
        acc.w += (v0.w + v1.w) + (v2.w + v3.w);
    }
    for (; e < end; e++) {
        const float4 v = h4[(size_t)g_esrc[e] * 64 + f4];
        acc.x += v.x; acc.y += v.y; acc.z += v.z; acc.w += v.w;
    }
    out4[(size_t)node * 64 + f4] = acc;
}

// ---------------------------------------------------------------------------
// Pull-mode aggregation, D=40 (+ReLU): 8 nodes per 320-thread block.
// ---------------------------------------------------------------------------
__global__ void agg40_relu(const float* __restrict__ h, float* __restrict__ out)
{
    const int tid = threadIdx.x;
    const int node = blockIdx.x * 8 + tid / NC;
    const int f = tid % NC;
    if (node >= NN) return;
    const int beg = g_off[node], end = g_off[node + 1];

    float acc = 0.f;
    int e = beg;
    for (; e + 4 <= end; e += 4) {
        const int s0 = g_esrc[e + 0], s1 = g_esrc[e + 1];
        const int s2 = g_esrc[e + 2], s3 = g_esrc[e + 3];
        const float v0 = h[(size_t)s0 * NC + f];
        const float v1 = h[(size_t)s1 * NC + f];
        const float v2 = h[(size_t)s2 * NC + f];
        const float v3 = h[(size_t)s3 * NC + f];
        acc += (v0 + v1) + (v2 + v3);
    }
    for (; e < end; e++)
        acc += h[(size_t)g_esrc[e] * NC + f];
    out[(size_t)node * NC + f] = fmaxf(acc, 0.f);
}

// ---------------------------------------------------------------------------
extern "C" void kernel_launch(void* const* d_in, const int* in_sizes, int n_in,
                              void* d_out, int out_size)
{
    const float* x  = (const float*)d_in[0];
    const void*  ei = d_in[1];
    const float* W1 = (const float*)d_in[2];
    const float* b1 = (const float*)d_in[3];
    const float* W2 = (const float*)d_in[4];
    const float* b2 = (const float*)d_in[5];
    const float* W3 = (const float*)d_in[6];
    const float* b3 = (const float*)d_in[7];
    float* out = (float*)d_out;

    float4 *buf0, *buf1, *buf2;
    cudaGetSymbolAddress((void**)&buf0, g_buf0);
    cudaGetSymbolAddress((void**)&buf1, g_buf1);
    cudaGetSymbolAddress((void**)&buf2, g_buf2);
    float* f0 = (float*)buf0;
    float* f1 = (float*)buf1;
    float* f2 = (float*)buf2;

    static cudaStream_t s_side = nullptr;
    static cudaEvent_t ev_fork = nullptr, ev_csr = nullptr;
    static cudaEvent_t ev_a1a = nullptr, ev_g2b = nullptr;
    static cudaEvent_t ev_a2a = nullptr, ev_g3b = nullptr;
    if (s_side == nullptr) {
        cudaStreamCreateWithFlags(&s_side, cudaStreamNonBlocking);
        cudaEventCreateWithFlags(&ev_fork, cudaEventDisableTiming);
        cudaEventCreateWithFlags(&ev_csr,  cudaEventDisableTiming);
        cudaEventCreateWithFlags(&ev_a1a,  cudaEventDisableTiming);
        cudaEventCreateWithFlags(&ev_g2b,  cudaEventDisableTiming);
        cudaEventCreateWithFlags(&ev_a2a,  cudaEventDisableTiming);
        cudaEventCreateWithFlags(&ev_g3b,  cudaEventDisableTiming);
    }

    const dim3 blk(256);
    const dim3 gFull(4, (NN + 127) / 128);   // (4, 79)
    const dim3 gHalf(4, (NH + 127) / 128);   // (4, 40)
    const dim3 gC64h(1, (NH + 63) / 64);     // (1, 79)
    const int aggHalfBlocks = NH / 4;        // 1250

    // ---- Fork: CSR build on side stream ----
    cudaEventRecord(ev_fork, 0);
    cudaStreamWaitEvent(s_side, ev_fork, 0);
    detect_and_zero<<<(NN + 255) / 256, blk, 0, s_side>>>((const int*)ei);
    convert_hist<<<(2 * NE + 255) / 256, blk, 0, s_side>>>(ei);
    scan_deg_fast<<<1, 1024, 0, s_side>>>();
    fill_csr<<<(NE + 255) / 256, blk, 0, s_side>>>();
    cudaEventRecord(ev_csr, s_side);

    // ---- Layer 1: GEMM (full) on main, overlapping CSR ----
    gemm128x64<false><<<gFull, blk>>>(x, W1, b1, f0, NN);
    cudaStreamWaitEvent(0, ev_csr, 0);

    // ---- agg1a (nodes 0..NH) on main ----
    agg256v<<<aggHalfBlocks, blk>>>(buf0, buf1, 0, NH);
    cudaEventRecord(ev_a1a, 0);

    // ---- GEMM2a (rows 0..NH) on main, overlapped with agg1b on side ----
    gemm128x64<true><<<gHalf, blk>>>(f1, W2, b2, f2, NH);

    cudaStreamWaitEvent(s_side, ev_a1a, 0);
    agg256v<<<aggHalfBlocks, blk, 0, s_side>>>(buf0, buf1, NH, NN - NH);
    gemm128x64<true><<<gHalf, blk, 0, s_side>>>(f1 + (size_t)NH * DH, W2, b2,
                                                f2 + (size_t)NH * DH, NN - NH);
    cudaEventRecord(ev_g2b, s_side);

    // ---- agg2a on main (needs all of GEMM2: main has 2a, wait for 2b) ----
    cudaStreamWaitEvent(0, ev_g2b, 0);
    agg256v<<<aggHalfBlocks, blk>>>(buf2, buf0, 0, NH);
    cudaEventRecord(ev_a2a, 0);

    // ---- GEMM3a on main, overlapped with agg2b + GEMM3b on side ----
    gemm64<true><<<gC64h, blk>>>(f0, W3, b3, f1, NH, NC, DH);

    cudaStreamWaitEvent(s_side, ev_a2a, 0);
    agg256v<<<aggHalfBlocks, blk, 0, s_side>>>(buf2, buf0, NH, NN - NH);
    gemm64<true><<<gC64h, blk, 0, s_side>>>(f0 + (size_t)NH * DH, W3, b3,
                                            f1 + (size_t)NH * NC, NN - NH, NC, DH);
    cudaEventRecord(ev_g3b, s_side);

    // ---- Final aggregation (+ReLU) -> out ----
    cudaStreamWaitEvent(0, ev_g3b, 0);
    agg40_relu<<<(NN + 7) / 8, 320>>>(f1, out);
}